// round 5
// baseline (speedup 1.0000x reference)
#include <cuda_runtime.h>
#include <cuda_bf16.h>
#include <mma.h>
#include <cstdint>
#include <math.h>

using namespace nvcuda;

#define B_ 32
#define N_ 8192
#define D_ 1024
#define H_ 128
#define NSPLIT 32

// ---------------- scratch (no cudaMalloc allowed) ----------------
__device__ __align__(16) unsigned short g_w1t_hi[H_ * D_];
__device__ __align__(16) unsigned short g_w1t_lo[H_ * D_];
__device__ __align__(16) float g_logits[B_ * N_];
__device__ __align__(16) float g_part[B_ * NSPLIT * D_];

// ---------------- helpers ----------------
__device__ __forceinline__ uint32_t smem_u32(const void* p) {
    uint32_t a;
    asm("{ .reg .u64 t; cvta.to.shared.u64 t, %1; cvt.u32.u64 %0, t; }" : "=r"(a) : "l"(p));
    return a;
}
__device__ __forceinline__ void cpasync16(uint32_t dst, const void* src) {
    asm volatile("cp.async.cg.shared.global [%0], [%1], 16;"
                 :: "r"(dst), "l"(src) : "memory");
}
__device__ __forceinline__ uint32_t pack_bf2(float a, float b) {
    unsigned short ua = __bfloat16_as_ushort(__float2bfloat16(a));
    unsigned short ub = __bfloat16_as_ushort(__float2bfloat16(b));
    return (uint32_t)ua | ((uint32_t)ub << 16);
}

// ---------------- kernel 0: W1^T -> bf16 hi/lo split ----------------
__global__ void prep_kernel(const float* __restrict__ w1) {
    int idx = blockIdx.x * 256 + threadIdx.x;   // 0..H*D-1
    int h = idx >> 10, d = idx & 1023;
    float x = w1[(size_t)d * H_ + h];           // w1 is [D][H]
    uint32_t ux = __float_as_uint(x);
    g_w1t_hi[idx] = (unsigned short)(ux >> 16);
    float lo = x - __uint_as_float(ux & 0xFFFF0000u);
    g_w1t_lo[idx] = __bfloat16_as_ushort(__float2bfloat16(lo));
}

// ---------------- kernel 1: fused GEMM1 + tanh + fc2 (wmma) ----------------
static constexpr int ROWE = 72;                  // row stride in bf16 elements
static constexpr int ROWB = 144;                 // row stride in bytes (128 data + 16 pad)
static constexpr int OFF_B1   = 0;               // 512 B
static constexpr int OFF_W2   = 512;             // 512 B
static constexpr int OFF_PART = 1024;            // 1024 B
static constexpr int OFF_SCR  = 2048;            // 8 warps * 256 floats = 8192 B
static constexpr int OFF_AHI  = 10240;
static constexpr int OFF_ALO  = OFF_AHI + 128 * ROWB;
static constexpr int OFF_BHI  = OFF_ALO + 128 * ROWB;
static constexpr int OFF_BLO  = OFF_BHI + 128 * ROWB;
static constexpr int SMEM_BYTES = OFF_BLO + 128 * ROWB;   // 83968

__global__ void __launch_bounds__(256)
gemm1_kernel(const float* __restrict__ feats, const float* __restrict__ b1,
             const float* __restrict__ w2, const float* __restrict__ b2) {
    extern __shared__ char dsm[];
    uint32_t sb = smem_u32(dsm);
    float* b1s  = (float*)(dsm + OFF_B1);
    float* w2s  = (float*)(dsm + OFF_W2);
    float* part = (float*)(dsm + OFF_PART);
    float* scr  = (float*)(dsm + OFF_SCR);
    __nv_bfloat16* Ahi = (__nv_bfloat16*)(dsm + OFF_AHI);
    __nv_bfloat16* Alo = (__nv_bfloat16*)(dsm + OFF_ALO);
    __nv_bfloat16* Bhi = (__nv_bfloat16*)(dsm + OFF_BHI);
    __nv_bfloat16* Blo = (__nv_bfloat16*)(dsm + OFF_BLO);

    int tid = threadIdx.x;
    int lane = tid & 31, warp = tid >> 5;
    int warp_m = warp >> 1, warp_n = warp & 1;   // 4 x 2 warp grid
    int m_base = warp_m * 32, n_base = warp_n * 64;

    if (tid < 128) { b1s[tid] = b1[tid]; w2s[tid] = w2[tid]; }

    const float* A0 = feats + (size_t)blockIdx.x * 128 * D_;

    // staging indices
    int ar = tid >> 4, ac4 = tid & 15;   // A: 8 iters x (row, float4-col)
    int bn = tid >> 3, bcu = tid & 7;    // B: 4 iters x (row, 16B-col)

    wmma::fragment<wmma::accumulator, 16, 16, 16, float> cfr[2][4];
    #pragma unroll
    for (int mi = 0; mi < 2; mi++)
        #pragma unroll
        for (int ni = 0; ni < 4; ni++)
            wmma::fill_fragment(cfr[mi][ni], 0.0f);

    auto ldg_a = [&](float4* av, int kc) {
        #pragma unroll
        for (int i = 0; i < 8; i++) {
            int r = ar + i * 16;
            av[i] = __ldg((const float4*)(A0 + (size_t)r * D_ + kc * 64) + ac4);
        }
    };
    auto sts_a = [&](const float4* av) {
        #pragma unroll
        for (int i = 0; i < 8; i++) {
            int r = ar + i * 16;
            uint32_t off = (uint32_t)(r * ROWB + ac4 * 8);
            uint32_t ax = __float_as_uint(av[i].x), ay = __float_as_uint(av[i].y);
            uint32_t az = __float_as_uint(av[i].z), aw = __float_as_uint(av[i].w);
            uint32_t h0 = (ax >> 16) | (ay & 0xFFFF0000u);
            uint32_t h1 = (az >> 16) | (aw & 0xFFFF0000u);
            float lx = av[i].x - __uint_as_float(ax & 0xFFFF0000u);
            float ly = av[i].y - __uint_as_float(ay & 0xFFFF0000u);
            float lz = av[i].z - __uint_as_float(az & 0xFFFF0000u);
            float lw = av[i].w - __uint_as_float(aw & 0xFFFF0000u);
            uint32_t l0 = pack_bf2(lx, ly), l1 = pack_bf2(lz, lw);
            asm volatile("st.shared.v2.b32 [%0], {%1, %2};"
                         :: "r"(sb + OFF_AHI + off), "r"(h0), "r"(h1) : "memory");
            asm volatile("st.shared.v2.b32 [%0], {%1, %2};"
                         :: "r"(sb + OFF_ALO + off), "r"(l0), "r"(l1) : "memory");
        }
    };
    auto cpa_b = [&](int kc) {
        #pragma unroll
        for (int i = 0; i < 4; i++) {
            int n = bn + i * 32;
            uint32_t doff = (uint32_t)(n * ROWB + bcu * 16);
            const unsigned short* sh = g_w1t_hi + (size_t)n * D_ + kc * 64 + bcu * 8;
            const unsigned short* sl = g_w1t_lo + (size_t)n * D_ + kc * 64 + bcu * 8;
            cpasync16(sb + OFF_BHI + doff, sh);
            cpasync16(sb + OFF_BLO + doff, sl);
        }
        asm volatile("cp.async.commit_group;" ::: "memory");
    };
    auto compute = [&]() {
        #pragma unroll
        for (int ks = 0; ks < 4; ks++) {
            wmma::fragment<wmma::matrix_a, 16, 16, 16, __nv_bfloat16, wmma::row_major> ah[2], al[2];
            #pragma unroll
            for (int mi = 0; mi < 2; mi++) {
                const __nv_bfloat16* pa = Ahi + (size_t)(m_base + mi * 16) * ROWE + ks * 16;
                const __nv_bfloat16* pl = Alo + (size_t)(m_base + mi * 16) * ROWE + ks * 16;
                wmma::load_matrix_sync(ah[mi], pa, ROWE);
                wmma::load_matrix_sync(al[mi], pl, ROWE);
            }
            #pragma unroll
            for (int ni = 0; ni < 4; ni++) {
                wmma::fragment<wmma::matrix_b, 16, 16, 16, __nv_bfloat16, wmma::col_major> bh, bl;
                const __nv_bfloat16* pb = Bhi + (size_t)(n_base + ni * 16) * ROWE + ks * 16;
                const __nv_bfloat16* pq = Blo + (size_t)(n_base + ni * 16) * ROWE + ks * 16;
                wmma::load_matrix_sync(bh, pb, ROWE);
                wmma::load_matrix_sync(bl, pq, ROWE);
                #pragma unroll
                for (int mi = 0; mi < 2; mi++) {
                    wmma::mma_sync(cfr[mi][ni], ah[mi], bh, cfr[mi][ni]);
                    wmma::mma_sync(cfr[mi][ni], ah[mi], bl, cfr[mi][ni]);
                    wmma::mma_sync(cfr[mi][ni], al[mi], bh, cfr[mi][ni]);
                }
            }
        }
    };

    // ---- prologue: stage chunk 0 ----
    {
        float4 av[8];
        ldg_a(av, 0);
        cpa_b(0);
        sts_a(av);
        asm volatile("cp.async.wait_group 0;" ::: "memory");
    }
    __syncthreads();

    // ---- main loop (single buffer, LDG prefetch overlaps compute) ----
    #pragma unroll 1
    for (int kc = 0; kc < 16; kc++) {
        float4 av[8];
        if (kc < 15) ldg_a(av, kc + 1);
        compute();
        __syncthreads();
        if (kc < 15) {
            sts_a(av);
            cpa_b(kc + 1);
            asm volatile("cp.async.wait_group 0;" ::: "memory");
        }
        __syncthreads();
    }

    // ---- epilogue: per-tile via smem scratch; p(row) = sum_j w2_j*tanh(c+b1_j) ----
    float* ws = scr + warp * 256;
    int r16 = lane & 15, ch = (lane >> 4) * 8;
    float pacc[2] = {0.0f, 0.0f};
    #pragma unroll
    for (int mi = 0; mi < 2; mi++) {
        #pragma unroll
        for (int ni = 0; ni < 4; ni++) {
            wmma::store_matrix_sync(ws, cfr[mi][ni], 16, wmma::mem_row_major);
            __syncwarp();
            float s = 0.0f;
            #pragma unroll
            for (int j = 0; j < 8; j++) {
                int col = n_base + ni * 16 + ch + j;
                float v = ws[r16 * 16 + ch + j];
                s += w2s[col] * tanhf(v + b1s[col]);
            }
            pacc[mi] += s;
            __syncwarp();
        }
    }
    #pragma unroll
    for (int mi = 0; mi < 2; mi++) {
        float tot = pacc[mi] + __shfl_xor_sync(0xffffffffu, pacc[mi], 16);
        if (lane < 16) {
            int row = m_base + mi * 16 + r16;
            part[row * 2 + warp_n] = tot;
        }
    }
    __syncthreads();
    if (tid < 128) {
        g_logits[(size_t)blockIdx.x * 128 + tid] =
            part[tid * 2] + part[tid * 2 + 1] + b2[0];
    }
}

// ---------------- kernel 2: masked softmax over N per batch ----------------
// mask is int32 (jnp.bool_ is converted; harness supports float32/int32/bf16 only)
__global__ void softmax_kernel(const int* __restrict__ mask,
                               float* __restrict__ attn) {
    __shared__ float red[1024];
    int b = blockIdx.x, t = threadIdx.x;
    const float* lg = g_logits + (size_t)b * N_;
    const int* mk = mask + (size_t)b * N_;

    float li[8], mv[8], mx = -3.4e38f;
    #pragma unroll
    for (int i = 0; i < 8; i++) {
        int n = t + i * 1024;
        float m = (mk[n] != 0) ? 1.0f : 0.0f;
        mv[i] = m;
        li[i] = (m != 0.0f) ? lg[n] : -1e9f;
        mx = fmaxf(mx, li[i]);
    }
    red[t] = mx; __syncthreads();
    for (int o = 512; o > 0; o >>= 1) { if (t < o) red[t] = fmaxf(red[t], red[t + o]); __syncthreads(); }
    mx = red[0]; __syncthreads();

    float e[8], s = 0.0f;
    #pragma unroll
    for (int i = 0; i < 8; i++) { e[i] = expf(li[i] - mx); s += e[i]; }
    red[t] = s; __syncthreads();
    for (int o = 512; o > 0; o >>= 1) { if (t < o) red[t] += red[t + o]; __syncthreads(); }
    float S = red[0]; __syncthreads();

    float s2 = 0.0f;
    #pragma unroll
    for (int i = 0; i < 8; i++) { e[i] = e[i] / S * mv[i]; s2 += e[i]; }
    red[t] = s2; __syncthreads();
    for (int o = 512; o > 0; o >>= 1) { if (t < o) red[t] += red[t + o]; __syncthreads(); }
    float inv = 1.0f / fmaxf(red[0], 1e-8f);

    #pragma unroll
    for (int i = 0; i < 8; i++)
        attn[(size_t)b * N_ + t + i * 1024] = e[i] * inv;
}

// ---------------- kernel 3: pooled partials ----------------
__global__ void __launch_bounds__(256)
pooled_part_kernel(const float* __restrict__ feats, const float* __restrict__ attn) {
    __shared__ float sa[256];
    int b = blockIdx.x, s = blockIdx.y, t = threadIdx.x;
    size_t n0 = (size_t)s * 256;
    sa[t] = attn[(size_t)b * N_ + n0 + t];
    __syncthreads();
    const float4* fp = (const float4*)(feats + ((size_t)b * N_ + n0) * D_);
    float4 acc = make_float4(0.f, 0.f, 0.f, 0.f);
    #pragma unroll 4
    for (int n = 0; n < 256; n++) {
        float a = sa[n];
        float4 v = __ldg(fp + (size_t)n * 256 + t);
        acc.x += a * v.x; acc.y += a * v.y; acc.z += a * v.z; acc.w += a * v.w;
    }
    ((float4*)(g_part + ((size_t)b * NSPLIT + s) * D_))[t] = acc;
}

// ---------------- kernel 4: reduce partials -> pooled ----------------
__global__ void reduce_kernel(float* __restrict__ pooled) {
    int idx = blockIdx.x * 256 + threadIdx.x;
    int b = idx >> 10, d = idx & 1023;
    float acc = 0.0f;
    #pragma unroll
    for (int s = 0; s < NSPLIT; s++)
        acc += g_part[((size_t)b * NSPLIT + s) * D_ + d];
    pooled[idx] = acc;
}

// ---------------- kernel 5: final classifier ----------------
__global__ void final_kernel(const float* __restrict__ pooled,
                             const float* __restrict__ wc,
                             const float* __restrict__ bc,
                             float* __restrict__ logits) {
    __shared__ float red[256];
    int b = blockIdx.x, t = threadIdx.x;
    float acc = 0.0f;
    #pragma unroll
    for (int j = 0; j < 4; j++) {
        int d = t + j * 256;
        acc += pooled[(size_t)b * D_ + d] * wc[d];
    }
    red[t] = acc; __syncthreads();
    for (int o = 128; o > 0; o >>= 1) { if (t < o) red[t] += red[t + o]; __syncthreads(); }
    if (t == 0) logits[b] = red[0] + bc[0];
}

// ---------------- launch ----------------
extern "C" void kernel_launch(void* const* d_in, const int* in_sizes, int n_in,
                              void* d_out, int out_size) {
    const float* feats = (const float*)d_in[0];
    const int* mask = (const int*)d_in[1];       // jnp.bool_ -> int32
    const float* w1 = (const float*)d_in[2];
    const float* b1 = (const float*)d_in[3];
    const float* w2 = (const float*)d_in[4];
    const float* b2 = (const float*)d_in[5];
    const float* wc = (const float*)d_in[6];
    const float* bc = (const float*)d_in[7];

    float* out = (float*)d_out;
    float* out_logits = out;                 // [B]
    float* out_pooled = out + B_;            // [B, D]
    float* out_attn   = out + B_ + B_ * D_;  // [B, N]

    cudaFuncSetAttribute(gemm1_kernel,
                         cudaFuncAttributeMaxDynamicSharedMemorySize, SMEM_BYTES);

    prep_kernel<<<(H_ * D_) / 256, 256>>>(w1);
    gemm1_kernel<<<(B_ * N_) / 128, 256, SMEM_BYTES>>>(feats, b1, w2, b2);
    softmax_kernel<<<B_, 1024>>>(mask, out_attn);
    pooled_part_kernel<<<dim3(B_, NSPLIT), 256>>>(feats, out_attn);
    reduce_kernel<<<(B_ * D_) / 256, 256>>>(out_pooled);
    final_kernel<<<B_, 256>>>(out_pooled, wc, bc, out_logits);
}

// round 6
// speedup vs baseline: 1.4836x; 1.4836x over previous
#include <cuda_runtime.h>
#include <cuda_fp16.h>
#include <mma.h>
#include <cstdint>
#include <math.h>

using namespace nvcuda;

#define B_ 32
#define N_ 8192
#define D_ 1024
#define H_ 128
#define NSPLIT 32

// ---------------- scratch (no cudaMalloc allowed) ----------------
__device__ __align__(16) unsigned short g_w1t_hi[H_ * D_];   // fp16 hi of W1^T
__device__ __align__(16) unsigned short g_w1t_lo[H_ * D_];   // fp16 residual
__device__ __align__(16) float g_logits[B_ * N_];
__device__ __align__(16) float g_part[B_ * NSPLIT * D_];

// ---------------- helpers ----------------
__device__ __forceinline__ uint32_t smem_u32(const void* p) {
    uint32_t a;
    asm("{ .reg .u64 t; cvta.to.shared.u64 t, %1; cvt.u32.u64 %0, t; }" : "=r"(a) : "l"(p));
    return a;
}
__device__ __forceinline__ void cpasync16(uint32_t dst, const void* src) {
    asm volatile("cp.async.cg.shared.global [%0], [%1], 16;"
                 :: "r"(dst), "l"(src) : "memory");
}

// ---------------- kernel 0: W1^T -> fp16 hi + fp16 residual ----------------
__global__ void prep_kernel(const float* __restrict__ w1) {
    int idx = blockIdx.x * 256 + threadIdx.x;   // 0..H*D-1
    int h = idx >> 10, d = idx & 1023;
    float x = w1[(size_t)d * H_ + h];           // w1 is [D][H]
    __half hi = __float2half_rn(x);
    float lo = x - __half2float(hi);
    g_w1t_hi[idx] = __half_as_ushort(hi);
    g_w1t_lo[idx] = __half_as_ushort(__float2half_rn(lo));
}

// ---------------- kernel 1: fused GEMM1 + tanh + fc2 (wmma fp16) ----------------
// A: single fp16 (RN), B: 2-term fp16 (hi + residual), fp32 accum.
static constexpr int ROWE = 72;                  // row stride in fp16 elements
static constexpr int ROWB = 144;                 // row stride bytes (128 data + 16 pad)
static constexpr int TILE = 128 * ROWB;          // 18432 bytes per 128x64 tile
static constexpr int OFF_B1   = 0;               // 512 B
static constexpr int OFF_W2   = 512;             // 512 B
static constexpr int OFF_PART = 1024;            // 1024 B
static constexpr int OFF_SCR  = 2048;            // 8 warps * 256 floats = 8192 B
static constexpr int OFF_A    = 10240;           // A fp16 (single buffer)
static constexpr int OFF_BH0  = OFF_A + TILE;    // Bh double buffer
static constexpr int OFF_BH1  = OFF_BH0 + TILE;
static constexpr int OFF_BL0  = OFF_BH1 + TILE;
static constexpr int OFF_BL1  = OFF_BL0 + TILE;
static constexpr int SMEM_BYTES = OFF_BL1 + TILE;   // 102400

__global__ void __launch_bounds__(256, 2)
gemm1_kernel(const float* __restrict__ feats, const float* __restrict__ b1,
             const float* __restrict__ w2, const float* __restrict__ b2) {
    extern __shared__ char dsm[];
    uint32_t sb = smem_u32(dsm);
    float* b1s  = (float*)(dsm + OFF_B1);
    float* w2s  = (float*)(dsm + OFF_W2);
    float* part = (float*)(dsm + OFF_PART);
    float* scr  = (float*)(dsm + OFF_SCR);
    __half* As  = (__half*)(dsm + OFF_A);

    int tid = threadIdx.x;
    int lane = tid & 31, warp = tid >> 5;
    int warp_m = warp >> 1, warp_n = warp & 1;   // 4 x 2 warp grid
    int m_base = warp_m * 32, n_base = warp_n * 64;

    if (tid < 128) { b1s[tid] = b1[tid]; w2s[tid] = w2[tid]; }

    const float* A0 = feats + (size_t)blockIdx.x * 128 * D_;

    // staging indices
    int ar = tid >> 4, ac4 = tid & 15;   // A: 8 iters x (row, float4-col)
    int bn = tid >> 3, bcu = tid & 7;    // B: 4 iters x (row, 16B-col)

    wmma::fragment<wmma::accumulator, 16, 16, 16, float> cfr[2][4];
    #pragma unroll
    for (int mi = 0; mi < 2; mi++)
        #pragma unroll
        for (int ni = 0; ni < 4; ni++)
            wmma::fill_fragment(cfr[mi][ni], 0.0f);

    auto ldg_a = [&](float4* av, int kc) {
        #pragma unroll
        for (int i = 0; i < 8; i++) {
            int r = ar + i * 16;
            av[i] = __ldg((const float4*)(A0 + (size_t)r * D_ + kc * 64) + ac4);
        }
    };
    auto sts_a = [&](const float4* av) {
        #pragma unroll
        for (int i = 0; i < 8; i++) {
            int r = ar + i * 16;
            uint32_t off = (uint32_t)(r * ROWB + ac4 * 8);
            __half2 h01 = __floats2half2_rn(av[i].x, av[i].y);
            __half2 h23 = __floats2half2_rn(av[i].z, av[i].w);
            asm volatile("st.shared.v2.b32 [%0], {%1, %2};"
                         :: "r"(sb + OFF_A + off),
                            "r"(*(uint32_t*)&h01), "r"(*(uint32_t*)&h23) : "memory");
        }
    };
    auto cpa_b = [&](int kc, int buf) {
        uint32_t dbh = sb + (buf ? OFF_BH1 : OFF_BH0);
        uint32_t dbl = sb + (buf ? OFF_BL1 : OFF_BL0);
        #pragma unroll
        for (int i = 0; i < 4; i++) {
            int n = bn + i * 32;
            uint32_t doff = (uint32_t)(n * ROWB + bcu * 16);
            const unsigned short* sh = g_w1t_hi + (size_t)n * D_ + kc * 64 + bcu * 8;
            const unsigned short* sl = g_w1t_lo + (size_t)n * D_ + kc * 64 + bcu * 8;
            cpasync16(dbh + doff, sh);
            cpasync16(dbl + doff, sl);
        }
        asm volatile("cp.async.commit_group;" ::: "memory");
    };
    auto compute = [&](int buf) {
        const __half* Bh = (const __half*)(dsm + (buf ? OFF_BH1 : OFF_BH0));
        const __half* Bl = (const __half*)(dsm + (buf ? OFF_BL1 : OFF_BL0));
        #pragma unroll
        for (int ks = 0; ks < 4; ks++) {
            wmma::fragment<wmma::matrix_a, 16, 16, 16, __half, wmma::row_major> af[2];
            #pragma unroll
            for (int mi = 0; mi < 2; mi++) {
                const __half* pa = As + (size_t)(m_base + mi * 16) * ROWE + ks * 16;
                wmma::load_matrix_sync(af[mi], pa, ROWE);
            }
            #pragma unroll
            for (int ni = 0; ni < 4; ni++) {
                wmma::fragment<wmma::matrix_b, 16, 16, 16, __half, wmma::col_major> bh, bl;
                const __half* pb = Bh + (size_t)(n_base + ni * 16) * ROWE + ks * 16;
                const __half* pq = Bl + (size_t)(n_base + ni * 16) * ROWE + ks * 16;
                wmma::load_matrix_sync(bh, pb, ROWE);
                wmma::load_matrix_sync(bl, pq, ROWE);
                #pragma unroll
                for (int mi = 0; mi < 2; mi++) {
                    wmma::mma_sync(cfr[mi][ni], af[mi], bh, cfr[mi][ni]);
                    wmma::mma_sync(cfr[mi][ni], af[mi], bl, cfr[mi][ni]);
                }
            }
        }
    };

    // ---- prologue: stage chunk 0 ----
    {
        float4 av[8];
        cpa_b(0, 0);
        ldg_a(av, 0);
        sts_a(av);
        asm volatile("cp.async.wait_group 0;" ::: "memory");
    }
    __syncthreads();

    // ---- main loop: B double-buffered (fetch kc+1 during compute kc),
    //      A register-prefetched (LDG kc+1 before compute kc, STS after) ----
    #pragma unroll 1
    for (int kc = 0; kc < 16; kc++) {
        float4 av[8];
        if (kc < 15) {
            ldg_a(av, kc + 1);
            cpa_b(kc + 1, (kc + 1) & 1);
        }
        compute(kc & 1);
        __syncthreads();                 // A smem reads of chunk kc done
        if (kc < 15) {
            sts_a(av);
            asm volatile("cp.async.wait_group 0;" ::: "memory");
        }
        __syncthreads();
    }

    // ---- epilogue: p(row) = sum_j w2_j * tanh(c + b1_j) ----
    float* ws = scr + warp * 256;
    int r16 = lane & 15, ch = (lane >> 4) * 8;
    float pacc[2] = {0.0f, 0.0f};
    #pragma unroll
    for (int mi = 0; mi < 2; mi++) {
        #pragma unroll
        for (int ni = 0; ni < 4; ni++) {
            wmma::store_matrix_sync(ws, cfr[mi][ni], 16, wmma::mem_row_major);
            __syncwarp();
            float s = 0.0f;
            #pragma unroll
            for (int j = 0; j < 8; j++) {
                int col = n_base + ni * 16 + ch + j;
                float v = ws[r16 * 16 + ch + j];
                s += w2s[col] * tanhf(v + b1s[col]);
            }
            pacc[mi] += s;
            __syncwarp();
        }
    }
    #pragma unroll
    for (int mi = 0; mi < 2; mi++) {
        float tot = pacc[mi] + __shfl_xor_sync(0xffffffffu, pacc[mi], 16);
        if (lane < 16) {
            int row = m_base + mi * 16 + r16;
            part[row * 2 + warp_n] = tot;
        }
    }
    __syncthreads();
    if (tid < 128) {
        g_logits[(size_t)blockIdx.x * 128 + tid] =
            part[tid * 2] + part[tid * 2 + 1] + b2[0];
    }
}

// ---------------- kernel 2: masked softmax over N per batch ----------------
__global__ void softmax_kernel(const int* __restrict__ mask,
                               float* __restrict__ attn) {
    __shared__ float red[1024];
    int b = blockIdx.x, t = threadIdx.x;
    const float* lg = g_logits + (size_t)b * N_;
    const int* mk = mask + (size_t)b * N_;

    float li[8], mv[8], mx = -3.4e38f;
    #pragma unroll
    for (int i = 0; i < 8; i++) {
        int n = t + i * 1024;
        float m = (mk[n] != 0) ? 1.0f : 0.0f;
        mv[i] = m;
        li[i] = (m != 0.0f) ? lg[n] : -1e9f;
        mx = fmaxf(mx, li[i]);
    }
    red[t] = mx; __syncthreads();
    for (int o = 512; o > 0; o >>= 1) { if (t < o) red[t] = fmaxf(red[t], red[t + o]); __syncthreads(); }
    mx = red[0]; __syncthreads();

    float e[8], s = 0.0f;
    #pragma unroll
    for (int i = 0; i < 8; i++) { e[i] = expf(li[i] - mx); s += e[i]; }
    red[t] = s; __syncthreads();
    for (int o = 512; o > 0; o >>= 1) { if (t < o) red[t] += red[t + o]; __syncthreads(); }
    float S = red[0]; __syncthreads();

    float s2 = 0.0f;
    #pragma unroll
    for (int i = 0; i < 8; i++) { e[i] = e[i] / S * mv[i]; s2 += e[i]; }
    red[t] = s2; __syncthreads();
    for (int o = 512; o > 0; o >>= 1) { if (t < o) red[t] += red[t + o]; __syncthreads(); }
    float inv = 1.0f / fmaxf(red[0], 1e-8f);

    #pragma unroll
    for (int i = 0; i < 8; i++)
        attn[(size_t)b * N_ + t + i * 1024] = e[i] * inv;
}

// ---------------- kernel 3: pooled partials ----------------
__global__ void __launch_bounds__(256)
pooled_part_kernel(const float* __restrict__ feats, const float* __restrict__ attn) {
    __shared__ float sa[256];
    int b = blockIdx.x, s = blockIdx.y, t = threadIdx.x;
    size_t n0 = (size_t)s * 256;
    sa[t] = attn[(size_t)b * N_ + n0 + t];
    __syncthreads();
    const float4* fp = (const float4*)(feats + ((size_t)b * N_ + n0) * D_);
    float4 acc = make_float4(0.f, 0.f, 0.f, 0.f);
    #pragma unroll 4
    for (int n = 0; n < 256; n++) {
        float a = sa[n];
        float4 v = __ldg(fp + (size_t)n * 256 + t);
        acc.x += a * v.x; acc.y += a * v.y; acc.z += a * v.z; acc.w += a * v.w;
    }
    ((float4*)(g_part + ((size_t)b * NSPLIT + s) * D_))[t] = acc;
}

// ---------------- kernel 4: reduce partials -> pooled ----------------
__global__ void reduce_kernel(float* __restrict__ pooled) {
    int idx = blockIdx.x * 256 + threadIdx.x;
    int b = idx >> 10, d = idx & 1023;
    float acc = 0.0f;
    #pragma unroll
    for (int s = 0; s < NSPLIT; s++)
        acc += g_part[((size_t)b * NSPLIT + s) * D_ + d];
    pooled[idx] = acc;
}

// ---------------- kernel 5: final classifier ----------------
__global__ void final_kernel(const float* __restrict__ pooled,
                             const float* __restrict__ wc,
                             const float* __restrict__ bc,
                             float* __restrict__ logits) {
    __shared__ float red[256];
    int b = blockIdx.x, t = threadIdx.x;
    float acc = 0.0f;
    #pragma unroll
    for (int j = 0; j < 4; j++) {
        int d = t + j * 256;
        acc += pooled[(size_t)b * D_ + d] * wc[d];
    }
    red[t] = acc; __syncthreads();
    for (int o = 128; o > 0; o >>= 1) { if (t < o) red[t] += red[t + o]; __syncthreads(); }
    if (t == 0) logits[b] = red[0] + bc[0];
}

// ---------------- launch ----------------
extern "C" void kernel_launch(void* const* d_in, const int* in_sizes, int n_in,
                              void* d_out, int out_size) {
    const float* feats = (const float*)d_in[0];
    const int* mask = (const int*)d_in[1];       // jnp.bool_ -> int32
    const float* w1 = (const float*)d_in[2];
    const float* b1 = (const float*)d_in[3];
    const float* w2 = (const float*)d_in[4];
    const float* b2 = (const float*)d_in[5];
    const float* wc = (const float*)d_in[6];
    const float* bc = (const float*)d_in[7];

    float* out = (float*)d_out;
    float* out_logits = out;                 // [B]
    float* out_pooled = out + B_;            // [B, D]
    float* out_attn   = out + B_ + B_ * D_;  // [B, N]

    cudaFuncSetAttribute(gemm1_kernel,
                         cudaFuncAttributeMaxDynamicSharedMemorySize, SMEM_BYTES);

    prep_kernel<<<(H_ * D_) / 256, 256>>>(w1);
    gemm1_kernel<<<(B_ * N_) / 128, 256, SMEM_BYTES>>>(feats, b1, w2, b2);
    softmax_kernel<<<B_, 1024>>>(mask, out_attn);
    pooled_part_kernel<<<dim3(B_, NSPLIT), 256>>>(feats, out_attn);
    reduce_kernel<<<(B_ * D_) / 256, 256>>>(out_pooled);
    final_kernel<<<B_, 256>>>(out_pooled, wc, bc, out_logits);
}

// round 7
// speedup vs baseline: 2.1054x; 1.4190x over previous
#include <cuda_runtime.h>
#include <cuda_fp16.h>
#include <mma.h>
#include <cstdint>
#include <math.h>

using namespace nvcuda;

#define B_ 32
#define N_ 8192
#define D_ 1024
#define H_ 128
#define NSPLIT 32

// ---------------- scratch (no cudaMalloc allowed) ----------------
__device__ __align__(16) unsigned short g_w1t[H_ * D_];   // fp16 W1^T [h][d]
__device__ __align__(16) float g_logits[B_ * N_];
__device__ __align__(16) float g_part[B_ * NSPLIT * D_];

// ---------------- helpers ----------------
__device__ __forceinline__ uint32_t smem_u32(const void* p) {
    uint32_t a;
    asm("{ .reg .u64 t; cvta.to.shared.u64 t, %1; cvt.u32.u64 %0, t; }" : "=r"(a) : "l"(p));
    return a;
}
__device__ __forceinline__ void cpasync16(uint32_t dst, const void* src) {
    asm volatile("cp.async.cg.shared.global [%0], [%1], 16;"
                 :: "r"(dst), "l"(src) : "memory");
}

// ---------------- kernel 0: W1^T -> fp16 ----------------
__global__ void prep_kernel(const float* __restrict__ w1) {
    int idx = blockIdx.x * 256 + threadIdx.x;   // 0..H*D-1
    int h = idx >> 10, d = idx & 1023;
    g_w1t[idx] = __half_as_ushort(__float2half_rn(w1[(size_t)d * H_ + h]));
}

// ---------------- kernel 1: fused GEMM1 + tanh + fc2 (wmma fp16) ----------------
static constexpr int ROWE = 72;                  // row stride in fp16 elements
static constexpr int ROWB = 144;                 // row stride bytes (128 data + 16 pad)
static constexpr int TILE = 128 * ROWB;          // 18432 bytes per 128x64 tile
static constexpr int OFF_B1   = 0;               // 512 B
static constexpr int OFF_W2   = 512;             // 512 B
static constexpr int OFF_PART = 1024;            // 1024 B
static constexpr int OFF_SCR  = 2048;            // 8 warps * 256 floats = 8192 B
static constexpr int OFF_A0   = 10240;           // A fp16 ping-pong
static constexpr int OFF_A1   = OFF_A0 + TILE;
static constexpr int OFF_BB0  = OFF_A1 + TILE;   // B fp16 ping-pong
static constexpr int OFF_BB1  = OFF_BB0 + TILE;
static constexpr int SMEM_BYTES = OFF_BB1 + TILE;   // 83968

__global__ void __launch_bounds__(256, 2)
gemm1_kernel(const float* __restrict__ feats, const float* __restrict__ b1,
             const float* __restrict__ w2, const float* __restrict__ b2) {
    extern __shared__ char dsm[];
    uint32_t sb = smem_u32(dsm);
    float* b1s  = (float*)(dsm + OFF_B1);
    float* w2s  = (float*)(dsm + OFF_W2);
    float* part = (float*)(dsm + OFF_PART);
    float* scr  = (float*)(dsm + OFF_SCR);

    int tid = threadIdx.x;
    int lane = tid & 31, warp = tid >> 5;
    int warp_m = warp >> 1, warp_n = warp & 1;   // 4 x 2 warp grid
    int m_base = warp_m * 32, n_base = warp_n * 64;

    if (tid < 128) { b1s[tid] = b1[tid]; w2s[tid] = w2[tid]; }

    const float* A0 = feats + (size_t)blockIdx.x * 128 * D_;

    // staging indices
    int ar = tid >> 4, ac4 = tid & 15;   // A: 8 iters x (row, float4-col)
    int bn = tid >> 3, bcu = tid & 7;    // B: 4 iters x (row, 16B-col)

    wmma::fragment<wmma::accumulator, 16, 16, 16, float> cfr[2][4];
    #pragma unroll
    for (int mi = 0; mi < 2; mi++)
        #pragma unroll
        for (int ni = 0; ni < 4; ni++)
            wmma::fill_fragment(cfr[mi][ni], 0.0f);

    auto ldg_a = [&](float4* av, int kc) {
        #pragma unroll
        for (int i = 0; i < 8; i++) {
            int r = ar + i * 16;
            av[i] = __ldg((const float4*)(A0 + (size_t)r * D_ + kc * 64) + ac4);
        }
    };
    auto sts_a = [&](const float4* av, int buf) {
        uint32_t base = sb + (buf ? OFF_A1 : OFF_A0);
        #pragma unroll
        for (int i = 0; i < 8; i++) {
            int r = ar + i * 16;
            uint32_t off = (uint32_t)(r * ROWB + ac4 * 8);
            __half2 h01 = __floats2half2_rn(av[i].x, av[i].y);
            __half2 h23 = __floats2half2_rn(av[i].z, av[i].w);
            asm volatile("st.shared.v2.b32 [%0], {%1, %2};"
                         :: "r"(base + off),
                            "r"(*(uint32_t*)&h01), "r"(*(uint32_t*)&h23) : "memory");
        }
    };
    auto cpa_b = [&](int kc, int buf) {
        uint32_t dbb = sb + (buf ? OFF_BB1 : OFF_BB0);
        #pragma unroll
        for (int i = 0; i < 4; i++) {
            int n = bn + i * 32;
            uint32_t doff = (uint32_t)(n * ROWB + bcu * 16);
            const unsigned short* sh = g_w1t + (size_t)n * D_ + kc * 64 + bcu * 8;
            cpasync16(dbb + doff, sh);
        }
        asm volatile("cp.async.commit_group;" ::: "memory");
    };
    auto compute = [&](int buf) {
        const __half* As = (const __half*)(dsm + (buf ? OFF_A1 : OFF_A0));
        const __half* Bs = (const __half*)(dsm + (buf ? OFF_BB1 : OFF_BB0));
        #pragma unroll
        for (int ks = 0; ks < 4; ks++) {
            wmma::fragment<wmma::matrix_a, 16, 16, 16, __half, wmma::row_major> af[2];
            #pragma unroll
            for (int mi = 0; mi < 2; mi++) {
                const __half* pa = As + (size_t)(m_base + mi * 16) * ROWE + ks * 16;
                wmma::load_matrix_sync(af[mi], pa, ROWE);
            }
            #pragma unroll
            for (int ni = 0; ni < 4; ni++) {
                wmma::fragment<wmma::matrix_b, 16, 16, 16, __half, wmma::col_major> bf;
                const __half* pb = Bs + (size_t)(n_base + ni * 16) * ROWE + ks * 16;
                wmma::load_matrix_sync(bf, pb, ROWE);
                #pragma unroll
                for (int mi = 0; mi < 2; mi++)
                    wmma::mma_sync(cfr[mi][ni], af[mi], bf, cfr[mi][ni]);
            }
        }
    };

    // ---- prologue: stage chunk 0 into buffer 0 ----
    {
        float4 av[8];
        cpa_b(0, 0);
        ldg_a(av, 0);
        sts_a(av, 0);
        asm volatile("cp.async.wait_group 0;" ::: "memory");
    }
    __syncthreads();

    // ---- main loop: both A and B double-buffered, ONE sync per chunk ----
    #pragma unroll 1
    for (int kc = 0; kc < 16; kc++) {
        int buf = kc & 1;
        float4 av[8];
        if (kc < 15) {
            ldg_a(av, kc + 1);          // DRAM latency hides under compute
            cpa_b(kc + 1, buf ^ 1);     // B prefetch into idle buffer
        }
        compute(buf);
        if (kc < 15) {
            sts_a(av, buf ^ 1);         // writes idle buffer; no conflict
            asm volatile("cp.async.wait_group 0;" ::: "memory");
        }
        __syncthreads();
    }

    // ---- epilogue: p(row) = sum_j w2_j * tanh(c + b1_j) ----
    float* ws = scr + warp * 256;
    int r16 = lane & 15, ch = (lane >> 4) * 8;
    float pacc[2] = {0.0f, 0.0f};
    #pragma unroll
    for (int mi = 0; mi < 2; mi++) {
        #pragma unroll
        for (int ni = 0; ni < 4; ni++) {
            wmma::store_matrix_sync(ws, cfr[mi][ni], 16, wmma::mem_row_major);
            __syncwarp();
            float s = 0.0f;
            #pragma unroll
            for (int j = 0; j < 8; j++) {
                int col = n_base + ni * 16 + ch + j;
                float v = ws[r16 * 16 + ch + j];
                s += w2s[col] * tanhf(v + b1s[col]);
            }
            pacc[mi] += s;
            __syncwarp();
        }
    }
    #pragma unroll
    for (int mi = 0; mi < 2; mi++) {
        float tot = pacc[mi] + __shfl_xor_sync(0xffffffffu, pacc[mi], 16);
        if (lane < 16) {
            int row = m_base + mi * 16 + r16;
            part[row * 2 + warp_n] = tot;
        }
    }
    __syncthreads();
    if (tid < 128) {
        g_logits[(size_t)blockIdx.x * 128 + tid] =
            part[tid * 2] + part[tid * 2 + 1] + b2[0];
    }
}

// ---------------- kernel 2: masked softmax over N per batch ----------------
__global__ void softmax_kernel(const int* __restrict__ mask,
                               float* __restrict__ attn) {
    __shared__ float red[1024];
    int b = blockIdx.x, t = threadIdx.x;
    const float* lg = g_logits + (size_t)b * N_;
    const int* mk = mask + (size_t)b * N_;

    float li[8], mv[8], mx = -3.4e38f;
    #pragma unroll
    for (int i = 0; i < 8; i++) {
        int n = t + i * 1024;
        float m = (mk[n] != 0) ? 1.0f : 0.0f;
        mv[i] = m;
        li[i] = (m != 0.0f) ? lg[n] : -1e9f;
        mx = fmaxf(mx, li[i]);
    }
    red[t] = mx; __syncthreads();
    for (int o = 512; o > 0; o >>= 1) { if (t < o) red[t] = fmaxf(red[t], red[t + o]); __syncthreads(); }
    mx = red[0]; __syncthreads();

    float e[8], s = 0.0f;
    #pragma unroll
    for (int i = 0; i < 8; i++) { e[i] = expf(li[i] - mx); s += e[i]; }
    red[t] = s; __syncthreads();
    for (int o = 512; o > 0; o >>= 1) { if (t < o) red[t] += red[t + o]; __syncthreads(); }
    float S = red[0]; __syncthreads();

    float s2 = 0.0f;
    #pragma unroll
    for (int i = 0; i < 8; i++) { e[i] = e[i] / S * mv[i]; s2 += e[i]; }
    red[t] = s2; __syncthreads();
    for (int o = 512; o > 0; o >>= 1) { if (t < o) red[t] += red[t + o]; __syncthreads(); }
    float inv = 1.0f / fmaxf(red[0], 1e-8f);

    #pragma unroll
    for (int i = 0; i < 8; i++)
        attn[(size_t)b * N_ + t + i * 1024] = e[i] * inv;
}

// ---------------- kernel 3: pooled partials ----------------
__global__ void __launch_bounds__(256)
pooled_part_kernel(const float* __restrict__ feats, const float* __restrict__ attn) {
    __shared__ float sa[256];
    int b = blockIdx.x, s = blockIdx.y, t = threadIdx.x;
    size_t n0 = (size_t)s * 256;
    sa[t] = attn[(size_t)b * N_ + n0 + t];
    __syncthreads();
    const float4* fp = (const float4*)(feats + ((size_t)b * N_ + n0) * D_);
    float4 acc = make_float4(0.f, 0.f, 0.f, 0.f);
    #pragma unroll 4
    for (int n = 0; n < 256; n++) {
        float a = sa[n];
        float4 v = __ldg(fp + (size_t)n * 256 + t);
        acc.x += a * v.x; acc.y += a * v.y; acc.z += a * v.z; acc.w += a * v.w;
    }
    ((float4*)(g_part + ((size_t)b * NSPLIT + s) * D_))[t] = acc;
}

// ---------------- kernel 4: reduce partials -> pooled ----------------
__global__ void reduce_kernel(float* __restrict__ pooled) {
    int idx = blockIdx.x * 256 + threadIdx.x;
    int b = idx >> 10, d = idx & 1023;
    float acc = 0.0f;
    #pragma unroll
    for (int s = 0; s < NSPLIT; s++)
        acc += g_part[((size_t)b * NSPLIT + s) * D_ + d];
    pooled[idx] = acc;
}

// ---------------- kernel 5: final classifier ----------------
__global__ void final_kernel(const float* __restrict__ pooled,
                             const float* __restrict__ wc,
                             const float* __restrict__ bc,
                             float* __restrict__ logits) {
    __shared__ float red[256];
    int b = blockIdx.x, t = threadIdx.x;
    float acc = 0.0f;
    #pragma unroll
    for (int j = 0; j < 4; j++) {
        int d = t + j * 256;
        acc += pooled[(size_t)b * D_ + d] * wc[d];
    }
    red[t] = acc; __syncthreads();
    for (int o = 128; o > 0; o >>= 1) { if (t < o) red[t] += red[t + o]; __syncthreads(); }
    if (t == 0) logits[b] = red[0] + bc[0];
}

// ---------------- launch ----------------
extern "C" void kernel_launch(void* const* d_in, const int* in_sizes, int n_in,
                              void* d_out, int out_size) {
    const float* feats = (const float*)d_in[0];
    const int* mask = (const int*)d_in[1];       // jnp.bool_ -> int32
    const float* w1 = (const float*)d_in[2];
    const float* b1 = (const float*)d_in[3];
    const float* w2 = (const float*)d_in[4];
    const float* b2 = (const float*)d_in[5];
    const float* wc = (const float*)d_in[6];
    const float* bc = (const float*)d_in[7];

    float* out = (float*)d_out;
    float* out_logits = out;                 // [B]
    float* out_pooled = out + B_;            // [B, D]
    float* out_attn   = out + B_ + B_ * D_;  // [B, N]

    cudaFuncSetAttribute(gemm1_kernel,
                         cudaFuncAttributeMaxDynamicSharedMemorySize, SMEM_BYTES);

    prep_kernel<<<(H_ * D_) / 256, 256>>>(w1);
    gemm1_kernel<<<(B_ * N_) / 128, 256, SMEM_BYTES>>>(feats, b1, w2, b2);
    softmax_kernel<<<B_, 1024>>>(mask, out_attn);
    pooled_part_kernel<<<dim3(B_, NSPLIT), 256>>>(feats, out_attn);
    reduce_kernel<<<(B_ * D_) / 256, 256>>>(out_pooled);
    final_kernel<<<B_, 256>>>(out_pooled, wc, bc, out_logits);
}